// round 5
// baseline (speedup 1.0000x reference)
#include <cuda_runtime.h>
#include <math.h>

// MinervaEnhancedLoss — single fused kernel (last-CTA finalize).
// Inputs (metadata order): pred_output f32 [512,10,64,64], targets i32 [512,64,64],
//                          inputs i32 [512,64,64], strategic_reasoning f32 [512,128]
// Output: 10 float32 scalars.

namespace {
constexpr int Bn = 512;
constexpr int Cn = 10;
constexpr int Hn = 64;
constexpr int Wn = 64;
constexpr int HW = Hn * Wn;               // 4096
constexpr int NWIN = (Hn - 1) * (Wn - 1); // 3969
constexpr int NBITW = 313;                // 313*32 = 10016 bits >= 10^4 codes
constexpr int NTHREADS = 512;             // 2 pixel-groups of 4 per thread
constexpr int NWARPS = NTHREADS / 32;     // 16
}

// Per-sample partials + completion counter (device globals — no allocation).
__device__ float        g_focal_p[Bn];   // focal sum * strategic weight
__device__ int          g_inter_p[Bn];   // intersection count
__device__ int          g_flags_p[Bn];   // bit0 = exact match, bit1 = copy
__device__ int          g_uniq_p[Bn];    // unique 2x2 codes
__device__ float        g_sig_p[Bn];     // sigmoid sum over 128 reasoning values
__device__ unsigned int g_done = 0;      // CTAs finished (reset by finalizer)

__device__ __forceinline__ float f4get(const float4& f, int j) {
    return j == 0 ? f.x : j == 1 ? f.y : j == 2 ? f.z : f.w;
}

// Reduce two floats at once across the block. Results valid in thread 0.
__device__ __forceinline__ float2 blockReduceSum2(float a, float b, float2* sbuf) {
    #pragma unroll
    for (int o = 16; o > 0; o >>= 1) {
        a += __shfl_down_sync(0xffffffffu, a, o);
        b += __shfl_down_sync(0xffffffffu, b, o);
    }
    const int warp = threadIdx.x >> 5;
    if ((threadIdx.x & 31) == 0) sbuf[warp] = make_float2(a, b);
    __syncthreads();
    float2 v = (threadIdx.x < NWARPS) ? sbuf[threadIdx.x] : make_float2(0.f, 0.f);
    if (threadIdx.x < 32) {
        #pragma unroll
        for (int o = NWARPS / 2; o > 0; o >>= 1) {
            v.x += __shfl_down_sync(0xffffffffu, v.x, o);
            v.y += __shfl_down_sync(0xffffffffu, v.y, o);
        }
    }
    __syncthreads();
    return v;
}

__global__ __launch_bounds__(NTHREADS) void minerva_kernel(
    const float* __restrict__ pred,
    const int*   __restrict__ targets,
    const int*   __restrict__ inputs,
    const float* __restrict__ strat,
    float*       __restrict__ out)
{
    const int b   = blockIdx.x;
    const int tid = threadIdx.x;

    __shared__ unsigned int  s_pred32[HW / 4];   // packed argmax bytes
    __shared__ unsigned int  s_bm[NBITW];
    __shared__ float2        s_f2[NWARPS];
    __shared__ double        s_d[NWARPS];
    __shared__ unsigned int  s_present;
    __shared__ int           s_last;

    for (int i = tid; i < NBITW; i += NTHREADS) s_bm[i] = 0u;
    if (tid == 0) s_present = 0u;

    // Early creativity load: overlap its DRAM latency with the pixel loop.
    float strat_x = 0.f;
    if (tid < 128) strat_x = strat[b * 128 + tid];

    const float4* __restrict__ pb = reinterpret_cast<const float4*>(pred + (size_t)b * Cn * HW);
    const int4*   __restrict__ tb = reinterpret_cast<const int4*>(targets + b * HW);
    const int4*   __restrict__ ib = reinterpret_cast<const int4*>(inputs  + b * HW);

    float    focal = 0.f;
    int      inter = 0;
    unsigned pres  = 0u;
    int      alleq = 1;
    int      cpy   = 1;

    // 2 groups x 512 threads x 4 pixels = 4096 pixels; all loads LDG.128, coalesced.
    #pragma unroll
    for (int g = 0; g < 2; ++g) {
        const int p4 = g * NTHREADS + tid;       // float4 index within the sample
        float4 v[Cn];
        #pragma unroll
        for (int c = 0; c < Cn; ++c) v[c] = pb[c * (HW / 4) + p4];
        const int4 t4 = tb[p4];
        const int4 i4 = ib[p4];
        const int tg[4] = {t4.x, t4.y, t4.z, t4.w};
        const int ip[4] = {i4.x, i4.y, i4.z, i4.w};

        unsigned packed_bi = 0u;
        #pragma unroll
        for (int j = 0; j < 4; ++j) {
            // First-max argmax (matches jnp.argmax tie semantics).
            float best = f4get(v[0], j);
            int   bi   = 0;
            #pragma unroll
            for (int c = 1; c < Cn; ++c) {
                const float x = f4get(v[c], j);
                if (x > best) { best = x; bi = c; }
            }
            // Softmax CE at the target channel; reuse the target exp term.
            const int t = tg[j];
            float se = 0.f;
            float et = 0.f;   // exp(v[t]-best)
            float vt = 0.f;
            #pragma unroll
            for (int c = 0; c < Cn; ++c) {
                const float x = f4get(v[c], j);
                const float e = __expf(x - best);
                se += e;
                et = (c == t) ? e : et;
                vt = (c == t) ? x : vt;
            }
            const float d  = vt - best;              // <= 0
            const float ce = __logf(se) - d;
            const float pt = __fdividef(et, se);     // exp(-ce)
            const float om = 1.f - pt;
            focal += om * om * ce;

            pres |= 1u << t;
            const int eq = (bi == t);
            inter += eq;
            alleq &= eq;
            cpy   &= (bi == ip[j]);
            packed_bi |= (unsigned)bi << (8 * j);
        }
        s_pred32[p4] = packed_bi;                // one STS.32 per group
    }

    // Colors-present reduction (bitwise; sync collectives below publish it).
    {
        const unsigned wp = __reduce_or_sync(0xffffffffu, pres);
        if ((tid & 31) == 0) atomicOr(&s_present, wp);
    }

    // Block-wide AND flags (barriers: s_pred32/s_present now visible).
    const int all_eq  = __syncthreads_and(alleq);
    const int all_cpy = __syncthreads_and(cpy);

    // focal + intersection reduced together (inter <= 4096 is exact in fp32).
    const float2 fi = blockReduceSum2(focal, (float)inter, s_f2);

    // Pattern diversity: 2x2 window codes -> presence bitmap -> popcount.
    const unsigned char* s_pred = reinterpret_cast<const unsigned char*>(s_pred32);
    for (int idx = tid; idx < NWIN; idx += NTHREADS) {
        const int h = idx / (Wn - 1);
        const int w = idx - h * (Wn - 1);
        const int base = h * Wn + w;
        const int a  = s_pred[base];
        const int bq = s_pred[base + 1];
        const int cq = s_pred[base + Wn];
        const int dq = s_pred[base + Wn + 1];
        const int code = a * 1000 + bq * 100 + cq * 10 + dq;
        atomicOr(&s_bm[code >> 5], 1u << (code & 31));
    }
    __syncthreads();
    int uq = 0;
    for (int i = tid; i < NBITW; i += NTHREADS) uq += __popc(s_bm[i]);

    // Creativity: sigmoid over this sample's 128 reasoning values.
    float sg = 0.f;
    if (tid < 128) sg = __fdividef(1.f, 1.f + __expf(-strat_x));

    // unique-count + sigmoid reduced together (uq <= 3969 exact in fp32).
    const float2 us = blockReduceSum2((float)uq, sg, s_f2);

    if (tid == 0) {
        const float wgt = (__popc(s_present) > 3) ? 1.2f : 1.0f;
        g_focal_p[b] = fi.x * wgt;
        g_inter_p[b] = (int)fi.y;
        g_flags_p[b] = (all_eq ? 1 : 0) | (all_cpy ? 2 : 0);
        g_uniq_p[b]  = (int)us.x;
        g_sig_p[b]   = us.y;
        __threadfence();                       // publish partials before count
        const unsigned old = atomicAdd(&g_done, 1u);
        s_last = (old == (unsigned)(Bn - 1));
    }
    __syncthreads();
    if (!s_last) return;

    // ---- Last CTA: finalize (512 threads, one per sample) ----
    __threadfence();   // acquire all CTAs' partials

    const float fl = g_focal_p[tid];
    const int   ir = g_inter_p[tid];
    const int   fg = g_flags_p[tid];
    const int   uqp = g_uniq_p[tid];
    const float sgp = g_sig_p[tid];

    double acc[5];
    acc[0] = (double)fl;
    acc[1] = (double)ir;
    acc[2] = (double)((fg & 1) + ((fg >> 1) & 1) * 65536);  // exact | copy<<16
    acc[3] = (double)uqp;
    acc[4] = (double)sgp;

    double r[5];
    #pragma unroll
    for (int k = 0; k < 5; ++k) {
        double v = acc[k];
        #pragma unroll
        for (int o = 16; o > 0; o >>= 1) v += __shfl_down_sync(0xffffffffu, v, o);
        if ((tid & 31) == 0) s_d[tid >> 5] = v;
        __syncthreads();
        v = (tid < NWARPS) ? s_d[tid] : 0.0;
        if (tid < 32) {
            #pragma unroll
            for (int o = NWARPS / 2; o > 0; o >>= 1) v += __shfl_down_sync(0xffffffffu, v, o);
        }
        r[k] = v;
        __syncthreads();
    }

    if (tid == 0) {
        const double focal_sum = r[0];
        const double inter_sum = r[1];
        const long long packed = (long long)(r[2] + 0.5);
        const double exact_n   = (double)(packed & 0xFFFF);
        const double copy_n    = (double)(packed >> 16);
        const double uniq_sum  = r[3];
        const double sig_sum   = r[4];

        const double focal      = focal_sum / ((double)Bn * HW);
        const double transform  = (copy_n / Bn) * 0.2;
        const double sum_iou    = inter_sum / (double)HW;  // sum_b intersection_b/4096
        const double sum_comb   = 0.2 * exact_n + 0.8 * sum_iou;
        const double mean_comb  = sum_comb / (double)Bn;
        const double exact_bon  = fmax(-mean_comb * 5.0, -3.0);
        const double iou_mean   = inter_sum / ((double)Bn * HW);
        const double creativity = (sig_sum / ((double)Bn * 128.0)) * 0.15;
        const double diversity  = (uniq_sum / ((double)Bn * (double)NWIN)) * 0.02;
        const double gsf        = fmin((double)HW / 900.0, 1.0);  // = 1
        const double complexity = mean_comb * gsf * 0.05;

        double total = focal + transform + exact_bon - creativity - diversity - complexity;
        if (isnan(total) || isinf(total)) total = fmin(focal, 10.0);

        out[0] = (float)total;
        out[1] = (float)focal;
        out[2] = (float)transform;
        out[3] = (float)exact_bon;
        out[4] = (float)sum_comb;   // exact_count
        out[5] = (float)sum_comb;   // combined_matches.sum()
        out[6] = (float)iou_mean;
        out[7] = (float)creativity;
        out[8] = (float)diversity;
        out[9] = (float)complexity;

        g_done = 0;                 // reset for next graph replay (deterministic)
    }
}

extern "C" void kernel_launch(void* const* d_in, const int* in_sizes, int n_in,
                              void* d_out, int out_size) {
    const float* pred  = (const float*)d_in[0];
    const int*   tgt   = (const int*)d_in[1];
    const int*   inp   = (const int*)d_in[2];
    const float* strat = (const float*)d_in[3];
    float* out = (float*)d_out;

    minerva_kernel<<<Bn, NTHREADS>>>(pred, tgt, inp, strat, out);
}

// round 8
// speedup vs baseline: 1.0996x; 1.0996x over previous
#include <cuda_runtime.h>
#include <math.h>

// MinervaEnhancedLoss — single fused kernel (last-CTA finalize).
// Scalar one-pixel-per-iteration layout, hard 3 CTAs/SM via launch_bounds:
// latency hiding from 48 warps/SM instead of per-thread register pressure.
// Inputs: pred f32 [512,10,64,64], targets i32 [512,64,64],
//         inputs i32 [512,64,64], strategic_reasoning f32 [512,128]
// Output: 10 float32 scalars.

namespace {
constexpr int Bn = 512;
constexpr int Cn = 10;
constexpr int Hn = 64;
constexpr int Wn = 64;
constexpr int HW = Hn * Wn;               // 4096
constexpr int NWIN = (Hn - 1) * (Wn - 1); // 3969
constexpr int NBITW = 313;                // 313*32 = 10016 bits >= 10^4 codes
constexpr int NTHREADS = 512;
constexpr int NWARPS = NTHREADS / 32;     // 16
}

__device__ float        g_focal_p[Bn];
__device__ int          g_inter_p[Bn];
__device__ int          g_flags_p[Bn];    // bit0 = exact, bit1 = copy
__device__ int          g_uniq_p[Bn];
__device__ float        g_sig_p[Bn];
__device__ unsigned int g_done = 0;

// Reduce two floats at once across the block. Results valid in thread 0.
__device__ __forceinline__ float2 blockReduceSum2(float a, float b, float2* sbuf) {
    #pragma unroll
    for (int o = 16; o > 0; o >>= 1) {
        a += __shfl_down_sync(0xffffffffu, a, o);
        b += __shfl_down_sync(0xffffffffu, b, o);
    }
    const int warp = threadIdx.x >> 5;
    if ((threadIdx.x & 31) == 0) sbuf[warp] = make_float2(a, b);
    __syncthreads();
    float2 v = (threadIdx.x < NWARPS) ? sbuf[threadIdx.x] : make_float2(0.f, 0.f);
    if (threadIdx.x < 32) {
        #pragma unroll
        for (int o = NWARPS / 2; o > 0; o >>= 1) {
            v.x += __shfl_down_sync(0xffffffffu, v.x, o);
            v.y += __shfl_down_sync(0xffffffffu, v.y, o);
        }
    }
    __syncthreads();
    return v;
}

__global__ __launch_bounds__(NTHREADS, 3) void minerva_kernel(
    const float* __restrict__ pred,
    const int*   __restrict__ targets,
    const int*   __restrict__ inputs,
    const float* __restrict__ strat,
    float*       __restrict__ out)
{
    const int b   = blockIdx.x;
    const int tid = threadIdx.x;

    __shared__ unsigned char s_pred[HW];
    __shared__ unsigned int  s_bm[NBITW];
    __shared__ float2        s_f2[NWARPS];
    __shared__ double        s_d[NWARPS];
    __shared__ unsigned int  s_present;
    __shared__ int           s_last;

    for (int i = tid; i < NBITW; i += NTHREADS) s_bm[i] = 0u;
    if (tid == 0) s_present = 0u;

    // Early creativity load: overlap its DRAM latency with the pixel loop.
    float strat_x = 0.f;
    if (tid < 128) strat_x = strat[b * 128 + tid];

    const float* __restrict__ pb = pred + (size_t)b * Cn * HW;
    const int*   __restrict__ tb = targets + b * HW;
    const int*   __restrict__ ib = inputs  + b * HW;

    float    focal = 0.f;
    int      inter = 0;
    unsigned pres  = 0u;
    int      alleq = 1;
    int      cpy   = 1;

    // 8 pixels/thread, one per iteration; 10 independent coalesced LDG.32
    // per iteration (MLP=10). Hiding comes from 48 warps/SM (3 CTAs).
    #pragma unroll
    for (int it = 0; it < 8; ++it) {
        const int p = it * NTHREADS + tid;   // coalesced 4B loads

        float v[Cn];
        #pragma unroll
        for (int c = 0; c < Cn; ++c) v[c] = pb[c * HW + p];
        const int t  = tb[p];
        const int ip = ib[p];

        // First-max argmax (matches jnp.argmax tie semantics).
        float best = v[0];
        int   bi   = 0;
        #pragma unroll
        for (int c = 1; c < Cn; ++c) {
            if (v[c] > best) { best = v[c]; bi = c; }
        }
        // Softmax CE at the target channel; reuse the target exp term.
        float se = 0.f, et = 0.f, vt = 0.f;
        #pragma unroll
        for (int c = 0; c < Cn; ++c) {
            const float e = __expf(v[c] - best);
            se += e;
            et = (c == t) ? e : et;
            vt = (c == t) ? v[c] : vt;
        }
        const float d  = vt - best;              // <= 0
        const float ce = __logf(se) - d;
        const float pt = __fdividef(et, se);     // exp(-ce)
        const float om = 1.f - pt;
        focal += om * om * ce;

        pres |= 1u << t;
        const int eq = (bi == t);
        inter += eq;
        alleq &= eq;
        cpy   &= (bi == ip);
        s_pred[p] = (unsigned char)bi;
    }

    // Colors-present reduction.
    {
        const unsigned wp = __reduce_or_sync(0xffffffffu, pres);
        if ((tid & 31) == 0) atomicOr(&s_present, wp);
    }

    // Block-wide AND flags (barriers: s_pred/s_present now visible).
    const int all_eq  = __syncthreads_and(alleq);
    const int all_cpy = __syncthreads_and(cpy);

    // focal + intersection reduced together (inter <= 4096 exact in fp32).
    const float2 fi = blockReduceSum2(focal, (float)inter, s_f2);

    // Pattern diversity: 2x2 window codes -> presence bitmap -> popcount.
    for (int idx = tid; idx < NWIN; idx += NTHREADS) {
        const int h = idx / (Wn - 1);
        const int w = idx - h * (Wn - 1);
        const int base = h * Wn + w;
        const int a  = s_pred[base];
        const int bq = s_pred[base + 1];
        const int cq = s_pred[base + Wn];
        const int dq = s_pred[base + Wn + 1];
        const int code = a * 1000 + bq * 100 + cq * 10 + dq;
        atomicOr(&s_bm[code >> 5], 1u << (code & 31));
    }
    __syncthreads();
    int uq = 0;
    for (int i = tid; i < NBITW; i += NTHREADS) uq += __popc(s_bm[i]);

    // Creativity: sigmoid over this sample's 128 reasoning values.
    float sg = 0.f;
    if (tid < 128) sg = __fdividef(1.f, 1.f + __expf(-strat_x));

    // unique-count + sigmoid reduced together (uq <= 3969 exact in fp32).
    const float2 us = blockReduceSum2((float)uq, sg, s_f2);

    if (tid == 0) {
        const float wgt = (__popc(s_present) > 3) ? 1.2f : 1.0f;
        g_focal_p[b] = fi.x * wgt;
        g_inter_p[b] = (int)fi.y;
        g_flags_p[b] = (all_eq ? 1 : 0) | (all_cpy ? 2 : 0);
        g_uniq_p[b]  = (int)us.x;
        g_sig_p[b]   = us.y;
        __threadfence();                       // publish partials before count
        const unsigned old = atomicAdd(&g_done, 1u);
        s_last = (old == (unsigned)(Bn - 1));
    }
    __syncthreads();
    if (!s_last) return;

    // ---- Last CTA: finalize (512 threads, one per sample) ----
    __threadfence();   // acquire all CTAs' partials

    const float fl  = g_focal_p[tid];
    const int   ir  = g_inter_p[tid];
    const int   fg  = g_flags_p[tid];
    const int   uqp = g_uniq_p[tid];
    const float sgp = g_sig_p[tid];

    double acc[5];
    acc[0] = (double)fl;
    acc[1] = (double)ir;
    acc[2] = (double)((fg & 1) + ((fg >> 1) & 1) * 65536);  // exact | copy<<16
    acc[3] = (double)uqp;
    acc[4] = (double)sgp;

    double r[5];
    #pragma unroll
    for (int k = 0; k < 5; ++k) {
        double v = acc[k];
        #pragma unroll
        for (int o = 16; o > 0; o >>= 1) v += __shfl_down_sync(0xffffffffu, v, o);
        if ((tid & 31) == 0) s_d[tid >> 5] = v;
        __syncthreads();
        v = (tid < NWARPS) ? s_d[tid] : 0.0;
        if (tid < 32) {
            #pragma unroll
            for (int o = NWARPS / 2; o > 0; o >>= 1) v += __shfl_down_sync(0xffffffffu, v, o);
        }
        r[k] = v;
        __syncthreads();
    }

    if (tid == 0) {
        const double focal_sum = r[0];
        const double inter_sum = r[1];
        const long long packed = (long long)(r[2] + 0.5);
        const double exact_n   = (double)(packed & 0xFFFF);
        const double copy_n    = (double)(packed >> 16);
        const double uniq_sum  = r[3];
        const double sig_sum   = r[4];

        const double focal      = focal_sum / ((double)Bn * HW);
        const double transform  = (copy_n / Bn) * 0.2;
        const double sum_iou    = inter_sum / (double)HW;
        const double sum_comb   = 0.2 * exact_n + 0.8 * sum_iou;
        const double mean_comb  = sum_comb / (double)Bn;
        const double exact_bon  = fmax(-mean_comb * 5.0, -3.0);
        const double iou_mean   = inter_sum / ((double)Bn * HW);
        const double creativity = (sig_sum / ((double)Bn * 128.0)) * 0.15;
        const double diversity  = (uniq_sum / ((double)Bn * (double)NWIN)) * 0.02;
        const double gsf        = fmin((double)HW / 900.0, 1.0);  // = 1
        const double complexity = mean_comb * gsf * 0.05;

        double total = focal + transform + exact_bon - creativity - diversity - complexity;
        if (isnan(total) || isinf(total)) total = fmin(focal, 10.0);

        out[0] = (float)total;
        out[1] = (float)focal;
        out[2] = (float)transform;
        out[3] = (float)exact_bon;
        out[4] = (float)sum_comb;   // exact_count
        out[5] = (float)sum_comb;   // combined_matches.sum()
        out[6] = (float)iou_mean;
        out[7] = (float)creativity;
        out[8] = (float)diversity;
        out[9] = (float)complexity;

        g_done = 0;                 // reset for next graph replay (deterministic)
    }
}

extern "C" void kernel_launch(void* const* d_in, const int* in_sizes, int n_in,
                              void* d_out, int out_size) {
    const float* pred  = (const float*)d_in[0];
    const int*   tgt   = (const int*)d_in[1];
    const int*   inp   = (const int*)d_in[2];
    const float* strat = (const float*)d_in[3];
    float* out = (float*)d_out;

    minerva_kernel<<<Bn, NTHREADS>>>(pred, tgt, inp, strat, out);
}